// round 7
// baseline (speedup 1.0000x reference)
#include <cuda_runtime.h>
#include <cstdint>

#define KCH 4
#define INF 10
#define HH  20

// ---- packed f32x2 helpers (SASS FFMA2 path; only reachable via PTX) ----
__device__ __forceinline__ uint64_t fma2(uint64_t a, uint64_t b, uint64_t c) {
    uint64_t d;
    asm("fma.rn.f32x2 %0, %1, %2, %3;" : "=l"(d) : "l"(a), "l"(b), "l"(c));
    return d;
}
__device__ __forceinline__ uint64_t add2(uint64_t a, uint64_t b) {
    uint64_t d;
    asm("add.rn.f32x2 %0, %1, %2;" : "=l"(d) : "l"(a), "l"(b));
    return d;
}
__device__ __forceinline__ float hadd2(uint64_t a) {
    uint32_t lo, hi;
    asm("mov.b64 {%0, %1}, %2;" : "=r"(lo), "=r"(hi) : "l"(a));
    return __uint_as_float(lo) + __uint_as_float(hi);
}

__device__ __forceinline__ float sigf(float v) {
    return __fdividef(1.0f, 1.0f + __expf(-v));
}
// NaN-safe fast tanh: exp argument always <= 0
__device__ __forceinline__ float tanhfast(float v) {
    float t = __expf(-2.0f * fabsf(v));
    float r = __fdividef(1.0f - t, 1.0f + t);
    return copysignf(r, v);
}

// 16-pair dot (32 floats), dual accumulator chains. w: 8 x LDS.128 (broadcast).
__device__ __forceinline__ float dot16(const ulonglong2* __restrict__ w, const uint64_t* a) {
    uint64_t acc0 = 0ull, acc1 = 0ull;
    #pragma unroll
    for (int t = 0; t < 8; t++) {
        ulonglong2 ww = w[t];
        acc0 = fma2(ww.x, a[2 * t],     acc0);
        acc1 = fma2(ww.y, a[2 * t + 1], acc1);
    }
    return hadd2(add2(acc0, acc1));
}
// 10-pair dot (20 floats) for U_f rows (80B, 16B-aligned)
__device__ __forceinline__ float dot10(const ulonglong2* __restrict__ u, const uint64_t* h) {
    uint64_t acc0 = 0ull, acc1 = 0ull;
    #pragma unroll
    for (int t = 0; t < 5; t++) {
        ulonglong2 uu = u[t];
        acc0 = fma2(uu.x, h[2 * t],     acc0);
        acc1 = fma2(uu.y, h[2 * t + 1], acc1);
    }
    return hadd2(add2(acc0, acc1));
}
// 6-pair dot (12 floats, zero-padded) for W_f rows (64B-aligned)
__device__ __forceinline__ float dot6(const ulonglong2* __restrict__ w, const uint64_t* a) {
    uint64_t acc0 = 0ull, acc1 = 0ull;
    #pragma unroll
    for (int t = 0; t < 3; t++) {
        ulonglong2 ww = w[t];
        acc0 = fma2(ww.x, a[2 * t],     acc0);
        acc1 = fma2(ww.y, a[2 * t + 1], acc1);
    }
    return hadd2(add2(acc0, acc1));
}

__global__ __launch_bounds__(256, 2)
void treelstm_kernel(const float* __restrict__ x,
                     const float* __restrict__ hch,
                     const float* __restrict__ cch,
                     const float* __restrict__ Wiou_w, const float* __restrict__ Wiou_b,
                     const float* __restrict__ Uiou_w, const float* __restrict__ Uiou_b,
                     const float* __restrict__ Wf_w,   const float* __restrict__ Wf_b,
                     const float* __restrict__ Uf_w,   const float* __restrict__ Uf_b,
                     float* __restrict__ out_h, float* __restrict__ out_c,
                     int n_nodes)
{
    // Weights in shared, biases pre-folded.
    // sWUiou row j (0..59), 128B: [W_iou row padded to 12 | U_iou row (20)]
    __shared__ __align__(16) float sWf[HH * 16];            // 1.25 KB
    __shared__ __align__(16) float sUf[HH * HH];            // 1.56 KB
    __shared__ __align__(16) float sWUiou[3 * HH * 32];     // 7.5 KB
    __shared__ float sBf[HH];                               // Wf_b + Uf_b
    __shared__ float sBiou[3 * HH];                         // Wiou_b + 4*Uiou_b
    __shared__ __align__(16) float sFx[HH * 256];           // 20 KB per-thread fx

    const int tid = threadIdx.x;

    for (int i = tid; i < HH * 16; i += blockDim.x) {
        int r = i >> 4, c = i & 15;
        sWf[i] = (c < INF) ? Wf_w[r * INF + c] : 0.0f;
    }
    for (int i = tid; i < 3 * HH * 32; i += blockDim.x) {
        int r = i >> 5, c = i & 31;
        float v;
        if (c < 12)      v = (c < INF) ? Wiou_w[r * INF + c] : 0.0f;
        else             v = Uiou_w[r * HH + (c - 12)];
        sWUiou[i] = v;
    }
    for (int i = tid; i < HH * HH; i += blockDim.x) sUf[i] = Uf_w[i];
    if (tid < HH)     sBf[tid]   = Wf_b[tid] + Uf_b[tid];
    if (tid < 3 * HH) sBiou[tid] = Wiou_b[tid] + 4.0f * Uiou_b[tid];
    __syncthreads();

    const int n = blockIdx.x * blockDim.x + tid;
    if (n >= n_nodes) return;

    // av = [x pairs (5), zero pad (1), hsum pairs (10)] — matches sWUiou row layout.
    // x pairs stay register-resident through the child phase (only av[6..15] mutate).
    uint64_t av[16];
    {
        const uint64_t* xp = (const uint64_t*)(x + (size_t)n * INF);
        #pragma unroll
        for (int q = 0; q < 5; q++) av[q] = xp[q];
        av[5] = 0ull;
        // fx_j = W_f x + b_wf + b_uf -> per-thread smem (stride-1, conflict-free)
        #pragma unroll
        for (int j = 0; j < HH; j++)
            sFx[j * 256 + tid] = dot6((const ulonglong2*)&sWf[j * 16], av) + sBf[j];
    }
    #pragma unroll
    for (int t = 6; t < 16; t++) av[t] = 0ull;   // hsum pairs

    float cacc[HH];
    #pragma unroll
    for (int j = 0; j < HH; j++) cacc[j] = 0.0f;

    // ---- children (NOT unrolled: one hk live at a time; all inner indices static) ----
    const char* hrow = (const char*)(hch + (size_t)n * HH);
    const char* crow = (const char*)(cch + (size_t)n * HH);
    const size_t kstride = (size_t)n_nodes * HH * sizeof(float);
    #pragma unroll 1
    for (int k = 0; k < KCH; k++) {
        uint64_t hk[10];
        const ulonglong2* hp = (const ulonglong2*)hrow;
        #pragma unroll
        for (int q = 0; q < 5; q++) {
            ulonglong2 v = hp[q];
            hk[2 * q]     = v.x;
            hk[2 * q + 1] = v.y;
        }
        #pragma unroll
        for (int t = 0; t < 10; t++) av[6 + t] = add2(av[6 + t], hk[t]);

        const float4* cp = (const float4*)crow;
        #pragma unroll
        for (int q = 0; q < 5; q++) {
            float4 cv = cp[q];
            float cvv[4] = {cv.x, cv.y, cv.z, cv.w};
            #pragma unroll
            for (int r = 0; r < 4; r++) {
                const int j = 4 * q + r;
                float a = dot10((const ulonglong2*)&sUf[j * HH], hk) + sFx[j * 256 + tid];
                cacc[j] += sigf(a) * cvv[r];
            }
        }
        hrow += kstride;
        crow += kstride;
    }

    // ---- iou gates + outputs (FULLY unrolled: cacc indices stay static) ----
    float* oh = out_h + (size_t)n * HH;
    float* oc = out_c + (size_t)n * HH;
    #pragma unroll
    for (int q = 0; q < 5; q++) {
        float res_h[4], res_c[4];
        #pragma unroll
        for (int r = 0; r < 4; r++) {
            const int j = 4 * q + r;
            float acc_i = dot16((const ulonglong2*)&sWUiou[(j)          * 32], av) + sBiou[j];
            float acc_o = dot16((const ulonglong2*)&sWUiou[(j + HH)     * 32], av) + sBiou[j + HH];
            float acc_u = dot16((const ulonglong2*)&sWUiou[(j + 2 * HH) * 32], av) + sBiou[j + 2 * HH];

            float cval = sigf(acc_i) * tanhfast(acc_u) + cacc[j];
            float hval = sigf(acc_o) * tanhfast(cval);
            res_c[r] = cval;
            res_h[r] = hval;
        }
        ((float4*)oh)[q] = make_float4(res_h[0], res_h[1], res_h[2], res_h[3]);
        ((float4*)oc)[q] = make_float4(res_c[0], res_c[1], res_c[2], res_c[3]);
    }
}

extern "C" void kernel_launch(void* const* d_in, const int* in_sizes, int n_in,
                              void* d_out, int out_size)
{
    const float* x      = (const float*)d_in[0];
    const float* hch    = (const float*)d_in[1];
    const float* cch    = (const float*)d_in[2];
    const float* Wiou_w = (const float*)d_in[3];
    const float* Wiou_b = (const float*)d_in[4];
    const float* Uiou_w = (const float*)d_in[5];
    const float* Uiou_b = (const float*)d_in[6];
    const float* Wf_w   = (const float*)d_in[7];
    const float* Wf_b   = (const float*)d_in[8];
    const float* Uf_w   = (const float*)d_in[9];
    const float* Uf_b   = (const float*)d_in[10];

    const int n_nodes = in_sizes[0] / INF;

    float* out_h = (float*)d_out;
    float* out_c = out_h + (size_t)n_nodes * HH;

    const int threads = 256;
    const int blocks = (n_nodes + threads - 1) / threads;

    treelstm_kernel<<<blocks, threads>>>(x, hch, cch,
                                         Wiou_w, Wiou_b, Uiou_w, Uiou_b,
                                         Wf_w, Wf_b, Uf_w, Uf_b,
                                         out_h, out_c, n_nodes);
}

// round 9
// speedup vs baseline: 1.2304x; 1.2304x over previous
#include <cuda_runtime.h>
#include <cstdint>

#define KCH 4
#define INF 10
#define HH  20

// ---- packed f32x2 helpers (SASS FFMA2 path; only reachable via PTX) ----
__device__ __forceinline__ uint64_t fma2(uint64_t a, uint64_t b, uint64_t c) {
    uint64_t d;
    asm("fma.rn.f32x2 %0, %1, %2, %3;" : "=l"(d) : "l"(a), "l"(b), "l"(c));
    return d;
}
__device__ __forceinline__ uint64_t add2(uint64_t a, uint64_t b) {
    uint64_t d;
    asm("add.rn.f32x2 %0, %1, %2;" : "=l"(d) : "l"(a), "l"(b));
    return d;
}
__device__ __forceinline__ float hadd2(uint64_t a) {
    uint32_t lo, hi;
    asm("mov.b64 {%0, %1}, %2;" : "=r"(lo), "=r"(hi) : "l"(a));
    return __uint_as_float(lo) + __uint_as_float(hi);
}

__device__ __forceinline__ float sigf(float v) {
    return __fdividef(1.0f, 1.0f + __expf(-v));
}
// NaN-safe fast tanh: exp argument always <= 0
__device__ __forceinline__ float tanhfast(float v) {
    float t = __expf(-2.0f * fabsf(v));
    float r = __fdividef(1.0f - t, 1.0f + t);
    return copysignf(r, v);
}

// 16-pair dot (32 floats), dual accumulator chains. w: 8 x LDS.128 (broadcast).
__device__ __forceinline__ float dot16(const ulonglong2* __restrict__ w, const uint64_t* a) {
    uint64_t acc0 = 0ull, acc1 = 0ull;
    #pragma unroll
    for (int t = 0; t < 8; t++) {
        ulonglong2 ww = w[t];
        acc0 = fma2(ww.x, a[2 * t],     acc0);
        acc1 = fma2(ww.y, a[2 * t + 1], acc1);
    }
    return hadd2(add2(acc0, acc1));
}
// 10-pair dot (20 floats) for U_f rows (80B, 16B-aligned)
__device__ __forceinline__ float dot10(const ulonglong2* __restrict__ u, const uint64_t* h) {
    uint64_t acc0 = 0ull, acc1 = 0ull;
    #pragma unroll
    for (int t = 0; t < 5; t++) {
        ulonglong2 uu = u[t];
        acc0 = fma2(uu.x, h[2 * t],     acc0);
        acc1 = fma2(uu.y, h[2 * t + 1], acc1);
    }
    return hadd2(add2(acc0, acc1));
}
// 6-pair dot (12 floats, zero-padded) for W_f rows (64B-aligned)
__device__ __forceinline__ float dot6(const ulonglong2* __restrict__ w, const uint64_t* a) {
    uint64_t acc0 = 0ull, acc1 = 0ull;
    #pragma unroll
    for (int t = 0; t < 3; t++) {
        ulonglong2 ww = w[t];
        acc0 = fma2(ww.x, a[2 * t],     acc0);
        acc1 = fma2(ww.y, a[2 * t + 1], acc1);
    }
    return hadd2(add2(acc0, acc1));
}

__global__ __launch_bounds__(256, 2)
void treelstm_kernel(const float* __restrict__ x,
                     const float* __restrict__ hch,
                     const float* __restrict__ cch,
                     const float* __restrict__ Wiou_w, const float* __restrict__ Wiou_b,
                     const float* __restrict__ Uiou_w, const float* __restrict__ Uiou_b,
                     const float* __restrict__ Wf_w,   const float* __restrict__ Wf_b,
                     const float* __restrict__ Uf_w,   const float* __restrict__ Uf_b,
                     float* __restrict__ out_h, float* __restrict__ out_c,
                     int n_nodes)
{
    // Weights in shared, biases pre-folded.
    // sWUiou row j (0..59), 128B: [W_iou row padded to 12 | U_iou row (20)]
    __shared__ __align__(16) float sWf[HH * 16];            // 1.25 KB
    __shared__ __align__(16) float sUf[HH * HH];            // 1.56 KB
    __shared__ __align__(16) float sWUiou[3 * HH * 32];     // 7.5 KB
    __shared__ float sBf[HH];                               // Wf_b + Uf_b
    __shared__ float sBiou[3 * HH];                         // Wiou_b + 4*Uiou_b
    __shared__ __align__(16) float sFx[HH * 256];           // 20 KB per-thread fx

    const int tid = threadIdx.x;

    for (int i = tid; i < HH * 16; i += blockDim.x) {
        int r = i >> 4, c = i & 15;
        sWf[i] = (c < INF) ? Wf_w[r * INF + c] : 0.0f;
    }
    for (int i = tid; i < 3 * HH * 32; i += blockDim.x) {
        int r = i >> 5, c = i & 31;
        float v;
        if (c < 12)      v = (c < INF) ? Wiou_w[r * INF + c] : 0.0f;
        else             v = Uiou_w[r * HH + (c - 12)];
        sWUiou[i] = v;
    }
    for (int i = tid; i < HH * HH; i += blockDim.x) sUf[i] = Uf_w[i];
    if (tid < HH)     sBf[tid]   = Wf_b[tid] + Uf_b[tid];
    if (tid < 3 * HH) sBiou[tid] = Wiou_b[tid] + 4.0f * Uiou_b[tid];
    __syncthreads();

    const int n = blockIdx.x * blockDim.x + tid;
    if (n >= n_nodes) return;

    const size_t kstride = (size_t)n_nodes * HH * sizeof(float);

    // ---- phase 0: load x pairs, fx_j -> per-thread smem ----
    // av = [x pairs (5), zero pad (1), hsum pairs (10)] — matches sWUiou row layout.
    uint64_t av[16];
    {
        const uint64_t* xp = (const uint64_t*)(x + (size_t)n * INF);
        #pragma unroll
        for (int q = 0; q < 5; q++) av[q] = xp[q];
        av[5] = 0ull;
        #pragma unroll
        for (int j = 0; j < HH; j++)
            sFx[j * 256 + tid] = dot6((const ulonglong2*)&sWf[j * 16], av) + sBf[j];
    }

    // ---- phase 1: hsum (no hk array kept live) ----
    #pragma unroll
    for (int t = 6; t < 16; t++) av[t] = 0ull;
    {
        const char* hrow = (const char*)(hch + (size_t)n * HH);
        #pragma unroll 1
        for (int k = 0; k < KCH; k++) {
            const ulonglong2* hp = (const ulonglong2*)hrow;
            #pragma unroll
            for (int q = 0; q < 5; q++) {
                ulonglong2 v = hp[q];
                av[6 + 2 * q]     = add2(av[6 + 2 * q],     v.x);
                av[6 + 2 * q + 1] = add2(av[6 + 2 * q + 1], v.y);
            }
            hrow += kstride;
        }
    }

    // ---- phase 2: iou gates; cpart = sig(i)*tanh(u), og = o-gate preact ----
    // After this phase av (x and hsum) is dead.
    float cpart[HH], og[HH];
    #pragma unroll
    for (int q = 0; q < 5; q++) {
        #pragma unroll
        for (int r = 0; r < 4; r++) {
            const int j = 4 * q + r;
            float acc_i = dot16((const ulonglong2*)&sWUiou[(j)          * 32], av) + sBiou[j];
            float acc_o = dot16((const ulonglong2*)&sWUiou[(j + HH)     * 32], av) + sBiou[j + HH];
            float acc_u = dot16((const ulonglong2*)&sWUiou[(j + 2 * HH) * 32], av) + sBiou[j + 2 * HH];
            cpart[j] = sigf(acc_i) * tanhfast(acc_u);
            og[j]    = acc_o;
        }
    }

    // ---- phase 3: per-child forget gates; cpart += sig(U_f h_k + fx_j) * c_k ----
    {
        const char* hrow = (const char*)(hch + (size_t)n * HH);
        const char* crow = (const char*)(cch + (size_t)n * HH);
        #pragma unroll 1
        for (int k = 0; k < KCH; k++) {
            uint64_t hk[10];
            const ulonglong2* hp = (const ulonglong2*)hrow;
            #pragma unroll
            for (int q = 0; q < 5; q++) {
                ulonglong2 v = hp[q];
                hk[2 * q]     = v.x;
                hk[2 * q + 1] = v.y;
            }
            const float4* cp = (const float4*)crow;
            #pragma unroll
            for (int q = 0; q < 5; q++) {
                float4 cv = cp[q];
                float cvv[4] = {cv.x, cv.y, cv.z, cv.w};
                #pragma unroll
                for (int r = 0; r < 4; r++) {
                    const int j = 4 * q + r;
                    float a = dot10((const ulonglong2*)&sUf[j * HH], hk) + sFx[j * 256 + tid];
                    cpart[j] += sigf(a) * cvv[r];
                }
            }
            hrow += kstride;
            crow += kstride;
        }
    }

    // ---- phase 4: outputs ----
    float* oh = out_h + (size_t)n * HH;
    float* oc = out_c + (size_t)n * HH;
    #pragma unroll
    for (int q = 0; q < 5; q++) {
        float res_h[4], res_c[4];
        #pragma unroll
        for (int r = 0; r < 4; r++) {
            const int j = 4 * q + r;
            res_c[r] = cpart[j];
            res_h[r] = sigf(og[j]) * tanhfast(cpart[j]);
        }
        ((float4*)oh)[q] = make_float4(res_h[0], res_h[1], res_h[2], res_h[3]);
        ((float4*)oc)[q] = make_float4(res_c[0], res_c[1], res_c[2], res_c[3]);
    }
}

extern "C" void kernel_launch(void* const* d_in, const int* in_sizes, int n_in,
                              void* d_out, int out_size)
{
    const float* x      = (const float*)d_in[0];
    const float* hch    = (const float*)d_in[1];
    const float* cch    = (const float*)d_in[2];
    const float* Wiou_w = (const float*)d_in[3];
    const float* Wiou_b = (const float*)d_in[4];
    const float* Uiou_w = (const float*)d_in[5];
    const float* Uiou_b = (const float*)d_in[6];
    const float* Wf_w   = (const float*)d_in[7];
    const float* Wf_b   = (const float*)d_in[8];
    const float* Uf_w   = (const float*)d_in[9];
    const float* Uf_b   = (const float*)d_in[10];

    const int n_nodes = in_sizes[0] / INF;

    float* out_h = (float*)d_out;
    float* out_c = out_h + (size_t)n_nodes * HH;

    const int threads = 256;
    const int blocks = (n_nodes + threads - 1) / threads;

    treelstm_kernel<<<blocks, threads>>>(x, hch, cch,
                                         Wiou_w, Wiou_b, Uiou_w, Uiou_b,
                                         Wf_w, Wf_b, Uf_w, Uf_b,
                                         out_h, out_c, n_nodes);
}

// round 12
// speedup vs baseline: 1.5389x; 1.2507x over previous
#include <cuda_runtime.h>
#include <cstdint>

#define KCH 4
#define INF 10
#define HH  20
#define JW  5                  // hidden units per thread (4 threads per node)
#define NODES_PER_BLK 64
#define IOU_STRIDE 36          // padded row (floats): [W(12) | U(20) | pad(4)], 144B

// ---- packed f32x2 helpers ----
__device__ __forceinline__ uint64_t fma2(uint64_t a, uint64_t b, uint64_t c) {
    uint64_t d;
    asm("fma.rn.f32x2 %0, %1, %2, %3;" : "=l"(d) : "l"(a), "l"(b), "l"(c));
    return d;
}
__device__ __forceinline__ uint64_t add2(uint64_t a, uint64_t b) {
    uint64_t d;
    asm("add.rn.f32x2 %0, %1, %2;" : "=l"(d) : "l"(a), "l"(b));
    return d;
}
__device__ __forceinline__ float hadd2(uint64_t a) {
    uint32_t lo, hi;
    asm("mov.b64 {%0, %1}, %2;" : "=r"(lo), "=r"(hi) : "l"(a));
    return __uint_as_float(lo) + __uint_as_float(hi);
}

__device__ __forceinline__ float sigf(float v) {
    return __fdividef(1.0f, 1.0f + __expf(-v));
}
// NaN-safe fast tanh: exp argument always <= 0
__device__ __forceinline__ float tanhfast(float v) {
    float t = __expf(-2.0f * fabsf(v));
    float r = __fdividef(1.0f - t, 1.0f + t);
    return copysignf(r, v);
}

// 16-pair dot (32 floats) vs av = [x(12) | hsum(20)]
__device__ __forceinline__ float dot16(const ulonglong2* __restrict__ w, const uint64_t* a) {
    uint64_t acc0 = 0ull, acc1 = 0ull;
    #pragma unroll
    for (int tt = 0; tt < 8; tt++) {
        ulonglong2 ww = w[tt];
        acc0 = fma2(ww.x, a[2 * tt],     acc0);
        acc1 = fma2(ww.y, a[2 * tt + 1], acc1);
    }
    return hadd2(add2(acc0, acc1));
}
// 10-pair dot (20 floats) for U_f rows (80B, 16B-aligned)
__device__ __forceinline__ float dot10(const ulonglong2* __restrict__ u, const uint64_t* h) {
    uint64_t acc0 = 0ull, acc1 = 0ull;
    #pragma unroll
    for (int tt = 0; tt < 5; tt++) {
        ulonglong2 uu = u[tt];
        acc0 = fma2(uu.x, h[2 * tt],     acc0);
        acc1 = fma2(uu.y, h[2 * tt + 1], acc1);
    }
    return hadd2(add2(acc0, acc1));
}
// 6-pair dot (12 floats, zero-padded) for W_f rows (64B-aligned)
__device__ __forceinline__ float dot6(const ulonglong2* __restrict__ w, const uint64_t* a) {
    uint64_t acc0 = 0ull, acc1 = 0ull;
    #pragma unroll
    for (int tt = 0; tt < 3; tt++) {
        ulonglong2 ww = w[tt];
        acc0 = fma2(ww.x, a[2 * tt],     acc0);
        acc1 = fma2(ww.y, a[2 * tt + 1], acc1);
    }
    return hadd2(add2(acc0, acc1));
}

__global__ __launch_bounds__(256)
void treelstm_kernel(const float* __restrict__ x,
                     const float* __restrict__ hch,
                     const float* __restrict__ cch,
                     const float* __restrict__ Wiou_w, const float* __restrict__ Wiou_b,
                     const float* __restrict__ Uiou_w, const float* __restrict__ Uiou_b,
                     const float* __restrict__ Wf_w,   const float* __restrict__ Wf_b,
                     const float* __restrict__ Uf_w,   const float* __restrict__ Uf_b,
                     float* __restrict__ out_h, float* __restrict__ out_c,
                     int n_nodes)
{
    __shared__ __align__(16) float sWf[HH * 16];                 // rows padded to 16
    __shared__ __align__(16) float sUf[HH * HH];                 // rows of 20 (80B)
    __shared__ __align__(16) float sWUiou[3 * HH * IOU_STRIDE];  // rows padded to 36 (144B)
    __shared__ float sBf[HH];                                    // Wf_b + Uf_b
    __shared__ float sBiou[3 * HH];                              // Wiou_b + 4*Uiou_b

    const int tid = threadIdx.x;

    for (int i = tid; i < HH * 16; i += blockDim.x) {
        int r = i >> 4, c = i & 15;
        sWf[i] = (c < INF) ? Wf_w[r * INF + c] : 0.0f;
    }
    for (int i = tid; i < 3 * HH * IOU_STRIDE; i += blockDim.x) {
        int r = i / IOU_STRIDE, c = i - r * IOU_STRIDE;
        float v = 0.0f;
        if (c < 12)      { if (c < INF) v = Wiou_w[r * INF + c]; }
        else if (c < 32) { v = Uiou_w[r * HH + (c - 12)]; }
        sWUiou[i] = v;
    }
    for (int i = tid; i < HH * HH; i += blockDim.x) sUf[i] = Uf_w[i];
    if (tid < HH)     sBf[tid]   = Wf_b[tid] + Uf_b[tid];
    if (tid < 3 * HH) sBiou[tid] = Wiou_b[tid] + 4.0f * Uiou_b[tid];
    __syncthreads();

    const int n  = blockIdx.x * NODES_PER_BLK + (tid >> 2);
    const int t  = tid & 3;
    const int j0 = t * JW;
    if (n >= n_nodes) return;

    const size_t kstride = (size_t)n_nodes * HH * sizeof(float);

    // av = [x pairs (5), zero pad (1), hsum pairs (10)] — matches sWUiou row layout
    uint64_t av[16];
    {
        const uint64_t* xp = (const uint64_t*)(x + (size_t)n * INF);
        #pragma unroll
        for (int q = 0; q < 5; q++) av[q] = xp[q];
        av[5] = 0ull;
    }

    // fx for this thread's 5 units (registers only)
    float fx[JW];
    #pragma unroll
    for (int jj = 0; jj < JW; jj++)
        fx[jj] = dot6((const ulonglong2*)&sWf[(j0 + jj) * 16], av) + sBf[j0 + jj];

    // hsum: accumulate directly into av[6..15]
    #pragma unroll
    for (int tt = 6; tt < 16; tt++) av[tt] = 0ull;
    {
        const char* hrow = (const char*)(hch + (size_t)n * HH);
        #pragma unroll 1
        for (int k = 0; k < KCH; k++) {
            const ulonglong2* hp = (const ulonglong2*)hrow;
            #pragma unroll
            for (int q = 0; q < 5; q++) {
                ulonglong2 v = hp[q];
                av[6 + 2 * q]     = add2(av[6 + 2 * q],     v.x);
                av[6 + 2 * q + 1] = add2(av[6 + 2 * q + 1], v.y);
            }
            hrow += kstride;
        }
    }

    // iou gates for this thread's 5 units: cpart = sig(i)*tanh(u), og = o preact
    float cpart[JW], og[JW];
    #pragma unroll
    for (int jj = 0; jj < JW; jj++) {
        const int j = j0 + jj;
        float acc_i = dot16((const ulonglong2*)&sWUiou[(j)          * IOU_STRIDE], av) + sBiou[j];
        float acc_o = dot16((const ulonglong2*)&sWUiou[(j + HH)     * IOU_STRIDE], av) + sBiou[j + HH];
        float acc_u = dot16((const ulonglong2*)&sWUiou[(j + 2 * HH) * IOU_STRIDE], av) + sBiou[j + 2 * HH];
        cpart[jj] = sigf(acc_i) * tanhfast(acc_u);
        og[jj]    = acc_o;
    }

    // per-child forget gates: cpart[jj] += sig(U_f h_k + fx[jj]) * c_k[j]
    {
        const char* hrow = (const char*)(hch + (size_t)n * HH);
        const char* crow = (const char*)(cch + ((size_t)n * HH + j0));
        #pragma unroll 1
        for (int k = 0; k < KCH; k++) {
            uint64_t hk[10];
            const ulonglong2* hp = (const ulonglong2*)hrow;
            #pragma unroll
            for (int q = 0; q < 5; q++) {
                ulonglong2 v = hp[q];
                hk[2 * q]     = v.x;
                hk[2 * q + 1] = v.y;
            }
            const float* cp = (const float*)crow;
            #pragma unroll
            for (int jj = 0; jj < JW; jj++) {
                float a = dot10((const ulonglong2*)&sUf[(j0 + jj) * HH], hk) + fx[jj];
                cpart[jj] += sigf(a) * cp[jj];
            }
            hrow += kstride;
            crow += kstride;
        }
    }

    // outputs: c = cpart; h = sig(og)*tanh(c)   (5 floats each, coalesced across group)
    float* oh = out_h + (size_t)n * HH + j0;
    float* oc = out_c + (size_t)n * HH + j0;
    #pragma unroll
    for (int jj = 0; jj < JW; jj++) {
        float cval = cpart[jj];
        oc[jj] = cval;
        oh[jj] = sigf(og[jj]) * tanhfast(cval);
    }
}

extern "C" void kernel_launch(void* const* d_in, const int* in_sizes, int n_in,
                              void* d_out, int out_size)
{
    const float* x      = (const float*)d_in[0];
    const float* hch    = (const float*)d_in[1];
    const float* cch    = (const float*)d_in[2];
    const float* Wiou_w = (const float*)d_in[3];
    const float* Wiou_b = (const float*)d_in[4];
    const float* Uiou_w = (const float*)d_in[5];
    const float* Uiou_b = (const float*)d_in[6];
    const float* Wf_w   = (const float*)d_in[7];
    const float* Wf_b   = (const float*)d_in[8];
    const float* Uf_w   = (const float*)d_in[9];
    const float* Uf_b   = (const float*)d_in[10];

    const int n_nodes = in_sizes[0] / INF;

    float* out_h = (float*)d_out;
    float* out_c = out_h + (size_t)n_nodes * HH;

    const int threads = 256;
    const int blocks = (n_nodes + NODES_PER_BLK - 1) / NODES_PER_BLK;

    treelstm_kernel<<<blocks, threads>>>(x, hch, cch,
                                         Wiou_w, Wiou_b, Uiou_w, Uiou_b,
                                         Wf_w, Wf_b, Uf_w, Uf_b,
                                         out_h, out_c, n_nodes);
}

// round 13
// speedup vs baseline: 2.1791x; 1.4160x over previous
#include <cuda_runtime.h>
#include <cstdint>

#define KCH 4
#define INF 10
#define HH  20
#define JW  5                  // hidden units per thread (4 threads per node)
#define NODES_PER_BLK 64
#define IOU_STRIDE 36          // padded row (floats): [W(12) | U(20) | pad(4)], 144B

// ---- packed f32x2 helpers ----
__device__ __forceinline__ uint64_t fma2(uint64_t a, uint64_t b, uint64_t c) {
    uint64_t d;
    asm("fma.rn.f32x2 %0, %1, %2, %3;" : "=l"(d) : "l"(a), "l"(b), "l"(c));
    return d;
}
__device__ __forceinline__ uint64_t add2(uint64_t a, uint64_t b) {
    uint64_t d;
    asm("add.rn.f32x2 %0, %1, %2;" : "=l"(d) : "l"(a), "l"(b));
    return d;
}
__device__ __forceinline__ float hadd2(uint64_t a) {
    uint32_t lo, hi;
    asm("mov.b64 {%0, %1}, %2;" : "=r"(lo), "=r"(hi) : "l"(a));
    return __uint_as_float(lo) + __uint_as_float(hi);
}

__device__ __forceinline__ float sigf(float v) {
    return __fdividef(1.0f, 1.0f + __expf(-v));
}
// NaN-safe fast tanh: exp argument always <= 0
__device__ __forceinline__ float tanhfast(float v) {
    float t = __expf(-2.0f * fabsf(v));
    float r = __fdividef(1.0f - t, 1.0f + t);
    return copysignf(r, v);
}

// 16-pair dot (32 floats) vs av = [x(12) | hsum(20)]
__device__ __forceinline__ float dot16(const ulonglong2* __restrict__ w, const uint64_t* a) {
    uint64_t acc0 = 0ull, acc1 = 0ull;
    #pragma unroll
    for (int tt = 0; tt < 8; tt++) {
        ulonglong2 ww = w[tt];
        acc0 = fma2(ww.x, a[2 * tt],     acc0);
        acc1 = fma2(ww.y, a[2 * tt + 1], acc1);
    }
    return hadd2(add2(acc0, acc1));
}
// 10-pair dot (20 floats) for U_f rows (80B, 16B-aligned)
__device__ __forceinline__ float dot10(const ulonglong2* __restrict__ u, const uint64_t* h) {
    uint64_t acc0 = 0ull, acc1 = 0ull;
    #pragma unroll
    for (int tt = 0; tt < 5; tt++) {
        ulonglong2 uu = u[tt];
        acc0 = fma2(uu.x, h[2 * tt],     acc0);
        acc1 = fma2(uu.y, h[2 * tt + 1], acc1);
    }
    return hadd2(add2(acc0, acc1));
}
// 6-pair dot (12 floats, zero-padded) for W_f rows (64B-aligned)
__device__ __forceinline__ float dot6(const ulonglong2* __restrict__ w, const uint64_t* a) {
    uint64_t acc0 = 0ull, acc1 = 0ull;
    #pragma unroll
    for (int tt = 0; tt < 3; tt++) {
        ulonglong2 ww = w[tt];
        acc0 = fma2(ww.x, a[2 * tt],     acc0);
        acc1 = fma2(ww.y, a[2 * tt + 1], acc1);
    }
    return hadd2(add2(acc0, acc1));
}

__global__ __launch_bounds__(256, 2)
void treelstm_kernel(const float* __restrict__ x,
                     const float* __restrict__ hch,
                     const float* __restrict__ cch,
                     const float* __restrict__ Wiou_w, const float* __restrict__ Wiou_b,
                     const float* __restrict__ Uiou_w, const float* __restrict__ Uiou_b,
                     const float* __restrict__ Wf_w,   const float* __restrict__ Wf_b,
                     const float* __restrict__ Uf_w,   const float* __restrict__ Uf_b,
                     float* __restrict__ out_h, float* __restrict__ out_c,
                     int n_nodes)
{
    __shared__ __align__(16) float sWf[HH * 16];                 // rows padded to 16
    __shared__ __align__(16) float sUf[HH * HH];                 // rows of 20 (80B)
    __shared__ __align__(16) float sWUiou[3 * HH * IOU_STRIDE];  // rows padded to 36 (144B)
    __shared__ float sBf[HH];                                    // Wf_b + Uf_b
    __shared__ float sBiou[3 * HH];                              // Wiou_b + 4*Uiou_b

    const int tid = threadIdx.x;

    for (int i = tid; i < HH * 16; i += blockDim.x) {
        int r = i >> 4, c = i & 15;
        sWf[i] = (c < INF) ? Wf_w[r * INF + c] : 0.0f;
    }
    for (int i = tid; i < 3 * HH * IOU_STRIDE; i += blockDim.x) {
        int r = i / IOU_STRIDE, c = i - r * IOU_STRIDE;
        float v = 0.0f;
        if (c < 12)      { if (c < INF) v = Wiou_w[r * INF + c]; }
        else if (c < 32) { v = Uiou_w[r * HH + (c - 12)]; }
        sWUiou[i] = v;
    }
    for (int i = tid; i < HH * HH; i += blockDim.x) sUf[i] = Uf_w[i];
    if (tid < HH)     sBf[tid]   = Wf_b[tid] + Uf_b[tid];
    if (tid < 3 * HH) sBiou[tid] = Wiou_b[tid] + 4.0f * Uiou_b[tid];
    __syncthreads();

    const int n  = blockIdx.x * NODES_PER_BLK + (tid >> 2);
    const int t  = tid & 3;
    const int j0 = t * JW;
    if (n >= n_nodes) return;

    const size_t kstride = (size_t)n_nodes * HH * sizeof(float);

    // av = [x pairs (5), zero pad (1), hsum pairs (10)] — matches sWUiou row layout
    uint64_t av[16];
    {
        const uint64_t* xp = (const uint64_t*)(x + (size_t)n * INF);
        #pragma unroll
        for (int q = 0; q < 5; q++) av[q] = xp[q];
        av[5] = 0ull;
    }

    // fx for this thread's 5 units (registers only)
    float fx[JW];
    #pragma unroll
    for (int jj = 0; jj < JW; jj++)
        fx[jj] = dot6((const ulonglong2*)&sWf[(j0 + jj) * 16], av) + sBf[j0 + jj];

    // hsum: accumulate directly into av[6..15]
    #pragma unroll
    for (int tt = 6; tt < 16; tt++) av[tt] = 0ull;
    {
        const char* hrow = (const char*)(hch + (size_t)n * HH);
        #pragma unroll 1
        for (int k = 0; k < KCH; k++) {
            const ulonglong2* hp = (const ulonglong2*)hrow;
            #pragma unroll
            for (int q = 0; q < 5; q++) {
                ulonglong2 v = hp[q];
                av[6 + 2 * q]     = add2(av[6 + 2 * q],     v.x);
                av[6 + 2 * q + 1] = add2(av[6 + 2 * q + 1], v.y);
            }
            hrow += kstride;
        }
    }

    // iou gates for this thread's 5 units: cpart = sig(i)*tanh(u), og = o preact
    float cpart[JW], og[JW];
    #pragma unroll
    for (int jj = 0; jj < JW; jj++) {
        const int j = j0 + jj;
        float acc_i = dot16((const ulonglong2*)&sWUiou[(j)          * IOU_STRIDE], av) + sBiou[j];
        float acc_o = dot16((const ulonglong2*)&sWUiou[(j + HH)     * IOU_STRIDE], av) + sBiou[j + HH];
        float acc_u = dot16((const ulonglong2*)&sWUiou[(j + 2 * HH) * IOU_STRIDE], av) + sBiou[j + 2 * HH];
        cpart[jj] = sigf(acc_i) * tanhfast(acc_u);
        og[jj]    = acc_o;
    }

    // per-child forget gates: cpart[jj] += sig(U_f h_k + fx[jj]) * c_k[j]
    {
        const char* hrow = (const char*)(hch + (size_t)n * HH);
        const char* crow = (const char*)(cch + ((size_t)n * HH + j0));
        #pragma unroll 1
        for (int k = 0; k < KCH; k++) {
            uint64_t hk[10];
            const ulonglong2* hp = (const ulonglong2*)hrow;
            #pragma unroll
            for (int q = 0; q < 5; q++) {
                ulonglong2 v = hp[q];
                hk[2 * q]     = v.x;
                hk[2 * q + 1] = v.y;
            }
            const float* cp = (const float*)crow;
            #pragma unroll
            for (int jj = 0; jj < JW; jj++) {
                float a = dot10((const ulonglong2*)&sUf[(j0 + jj) * HH], hk) + fx[jj];
                cpart[jj] += sigf(a) * cp[jj];
            }
            hrow += kstride;
            crow += kstride;
        }
    }

    // outputs: c = cpart; h = sig(og)*tanh(c)   (5 floats each, coalesced across group)
    float* oh = out_h + (size_t)n * HH + j0;
    float* oc = out_c + (size_t)n * HH + j0;
    #pragma unroll
    for (int jj = 0; jj < JW; jj++) {
        float cval = cpart[jj];
        oc[jj] = cval;
        oh[jj] = sigf(og[jj]) * tanhfast(cval);
    }
}

extern "C" void kernel_launch(void* const* d_in, const int* in_sizes, int n_in,
                              void* d_out, int out_size)
{
    const float* x      = (const float*)d_in[0];
    const float* hch    = (const float*)d_in[1];
    const float* cch    = (const float*)d_in[2];
    const float* Wiou_w = (const float*)d_in[3];
    const float* Wiou_b = (const float*)d_in[4];
    const float* Uiou_w = (const float*)d_in[5];
    const float* Uiou_b = (const float*)d_in[6];
    const float* Wf_w   = (const float*)d_in[7];
    const float* Wf_b   = (const float*)d_in[8];
    const float* Uf_w   = (const float*)d_in[9];
    const float* Uf_b   = (const float*)d_in[10];

    const int n_nodes = in_sizes[0] / INF;

    float* out_h = (float*)d_out;
    float* out_c = out_h + (size_t)n_nodes * HH;

    const int threads = 256;
    const int blocks = (n_nodes + NODES_PER_BLK - 1) / NODES_PER_BLK;

    treelstm_kernel<<<blocks, threads>>>(x, hch, cch,
                                         Wiou_w, Wiou_b, Uiou_w, Uiou_b,
                                         Wf_w, Wf_b, Uf_w, Uf_b,
                                         out_h, out_c, n_nodes);
}